// round 12
// baseline (speedup 1.0000x reference)
#include <cuda_runtime.h>
#include <cuda_fp16.h>
#include <math.h>

#ifndef M_PI
#define M_PI 3.14159265358979323846
#endif

#define BATCH 128
#define OUT   256
#define MB    8      // M branches
#define INS   512    // inner size
#define TI    16     // batch tile
#define TB    16     // out tile
#define KSH   416    // k in [0,416): MUFU f16x2 tanh path
#define KPF   (INS - KSH)   // 96: scalar-f32 FFMA polynomial path
#define KPH   (KSH + 8)     // f16 row pad
#define KPW   (KPF + 2)     // f32 row pad (even -> 8B aligned rows)
#define NCF   8      // poly: degree 15 odd in u (deg 7 in v=u^2), clamp |u|<=3

struct Coeffs { float c[NCF]; };

// scratch: S[i][b][j] = sum_k sigmoid(x[i,j,k]*W[b,j,k])
__device__ float g_S[BATCH * OUT * MB];

__device__ __forceinline__ __half2 tanh_h2(__half2 v) {
    unsigned r, a = *(unsigned*)&v;
    asm("tanh.approx.f16x2 %0, %1;" : "=r"(r) : "r"(a));
    return *(__half2*)&r;
}

// One CTA = (16 i x 16 b) tile of ONE branch j.
// sigmoid(u2) = 0.5 + 0.5*tanh(u2/2); x prescaled by 0.5 in smem (both regions).
// k < 416: MUFU tanh.approx.f16x2 (XU pipe, r4 proven body).
// k >= 416: scalar f32 Horner tanh(u) ~= u*P(u^2) on the FMA pipe.
__global__ __launch_bounds__(256) void dnm_main_kernel(
    const float* __restrict__ x,
    const float* __restrict__ w,
    Coeffs cf)
{
    __shared__ __half xh[TI][KPH];
    __shared__ __half wh[TB][KPH];
    __shared__ float  xf[TI][KPW];
    __shared__ float  wf[TB][KPW];

    const int tid = threadIdx.x;
    const int tx  = tid & 15;
    const int ty  = tid >> 4;
    const int i0  = blockIdx.x * TI;
    const int b0  = blockIdx.y * TB;
    const int j   = blockIdx.z;        // 1024 CTAs total

    // ---- loads: first 416 cols -> f16 tiles, last 96 -> f32 tiles ----
    #pragma unroll
    for (int it = 0; it < (TI * INS) / (4 * 256); ++it) {   // 8 iters
        int idx = it * 256 + tid;
        int r = idx >> 7, c4 = idx & 127;                   // 128 float4/row
        float4 v = *(const float4*)&x[((size_t)(i0 + r) * MB + j) * INS + (c4 << 2)];
        if (c4 < KSH / 4) {
            int c = c4 << 2;
            *(__half2*)&xh[r][c]     = __floats2half2_rn(0.5f * v.x, 0.5f * v.y);
            *(__half2*)&xh[r][c + 2] = __floats2half2_rn(0.5f * v.z, 0.5f * v.w);
        } else {
            int c = (c4 - KSH / 4) << 2;
            xf[r][c + 0] = 0.5f * v.x; xf[r][c + 1] = 0.5f * v.y;
            xf[r][c + 2] = 0.5f * v.z; xf[r][c + 3] = 0.5f * v.w;
        }
    }
    #pragma unroll
    for (int it = 0; it < (TB * INS) / (4 * 256); ++it) {
        int idx = it * 256 + tid;
        int r = idx >> 7, c4 = idx & 127;
        float4 v = *(const float4*)&w[((size_t)(b0 + r) * MB + j) * INS + (c4 << 2)];
        if (c4 < KSH / 4) {
            int c = c4 << 2;
            *(__half2*)&wh[r][c]     = __floats2half2_rn(v.x, v.y);
            *(__half2*)&wh[r][c + 2] = __floats2half2_rn(v.z, v.w);
        } else {
            int c = (c4 - KSH / 4) << 2;
            wf[r][c + 0] = v.x; wf[r][c + 1] = v.y;
            wf[r][c + 2] = v.z; wf[r][c + 3] = v.w;
        }
    }
    __syncthreads();

    // ---- MUFU segment (r4 proven body): 4 elems / iter ----
    float acc0 = 0.0f, acc1 = 0.0f;
    {
        const __half* xr = &xh[tx][0];
        const __half* wr = &wh[ty][0];
        #pragma unroll 8
        for (int k = 0; k < KSH; k += 4) {
            uint2 xv = *(const uint2*)&xr[k];
            uint2 wv = *(const uint2*)&wr[k];
            __half2 t01 = __hmul2(*(__half2*)&xv.x, *(__half2*)&wv.x);
            __half2 t23 = __hmul2(*(__half2*)&xv.y, *(__half2*)&wv.y);
            __half2 h01 = tanh_h2(t01);
            __half2 h23 = tanh_h2(t23);
            __half2 s   = __hadd2(h01, h23);
            acc0 += __low2float(s);
            acc1 += __high2float(s);
        }
    }

    // ---- poly segment: scalar f32, FMA pipe only ----
    float accP0 = 0.0f, accP1 = 0.0f;
    {
        const float* xr = &xf[tx][0];
        const float* wr = &wf[ty][0];
        #pragma unroll 8
        for (int k = 0; k < KPF; k += 2) {
            float2 xv = *(const float2*)&xr[k];
            float2 wv = *(const float2*)&wr[k];
            float t0 = xv.x * wv.x;
            float t1 = xv.y * wv.y;
            t0 = fminf(fmaxf(t0, -3.0f), 3.0f);
            t1 = fminf(fmaxf(t1, -3.0f), 3.0f);
            float v0 = t0 * t0;
            float v1 = t1 * t1;
            float P0 = cf.c[NCF - 1];
            float P1 = cf.c[NCF - 1];
            #pragma unroll
            for (int q = NCF - 2; q >= 0; --q) {
                P0 = fmaf(P0, v0, cf.c[q]);
                P1 = fmaf(P1, v1, cf.c[q]);
            }
            accP0 = fmaf(t0, P0, accP0);
            accP1 = fmaf(t1, P1, accP1);
        }
    }

    // sum_k sigmoid = 0.5 * sum_k tanh + 0.5 * INS
    float S = fmaf(0.5f, (acc0 + acc1) + (accP0 + accP1), 0.5f * (float)INS);
    g_S[((size_t)(i0 + tx) * OUT + (b0 + ty)) * MB + j] = S;
}

// Per-row normalize with fused product-of-branches (r4 proven version).
__global__ __launch_bounds__(OUT) void dnm_norm_kernel(float* __restrict__ out)
{
    const int i = blockIdx.x;
    const int b = threadIdx.x;

    const float* sp = &g_S[((size_t)i * OUT + b) * MB];
    float4 a = *(const float4*)sp;
    float4 c = *(const float4*)(sp + 4);
    float v = ((a.x * a.y) * (a.z * a.w)) * ((c.x * c.y) * (c.z * c.w));

    // v ~ 256^8 = 2^64 -> scale before squaring (stats are scale-invariant)
    float vs = v * 0x1p-64f;

    float s1 = vs, s2 = vs * vs;
    #pragma unroll
    for (int off = 16; off > 0; off >>= 1) {
        s1 += __shfl_xor_sync(0xffffffffu, s1, off);
        s2 += __shfl_xor_sync(0xffffffffu, s2, off);
    }
    __shared__ float r1[8], r2[8];
    if ((b & 31) == 0) { r1[b >> 5] = s1; r2[b >> 5] = s2; }
    __syncthreads();

    float total = 0.0f, sq = 0.0f;
    #pragma unroll
    for (int q = 0; q < 8; ++q) { total += r1[q]; sq += r2[q]; }

    float inv = 1.0f / total;
    float zn  = vs * inv;
    float var = (sq * inv * inv - 1.0f / 256.0f) * (1.0f / 255.0f);
    out[(size_t)i * OUT + b] = (zn - 1.0f / 256.0f) * rsqrtf(var);
}

extern "C" void kernel_launch(void* const* d_in, const int* in_sizes, int n_in,
                              void* d_out, int out_size)
{
    const float* x = (const float*)d_in[0];   // (128, 8, 512)
    const float* w = (const float*)d_in[1];   // (256, 8, 512)
    float* z = (float*)d_out;                 // (128, 256)

    // host-side Chebyshev-node interpolation of f(v) = tanh(sqrt(v))/sqrt(v)
    // on v in [0,9], degree NCF-1  ->  tanh(u) ~= u * P(u^2) for |u| <= 3.
    double vn[NCF], dd[NCF];
    for (int i = 0; i < NCF; ++i) {
        double th = M_PI * (2.0 * i + 1.0) / (2.0 * NCF);
        double v  = 4.5 * (1.0 - cos(th));
        double u  = sqrt(v);
        vn[i] = v;
        dd[i] = tanh(u) / u;
    }
    for (int jj = 1; jj < NCF; ++jj)
        for (int i = NCF - 1; i >= jj; --i)
            dd[i] = (dd[i] - dd[i - 1]) / (vn[i] - vn[i - jj]);
    double cm[NCF];
    for (int i = 0; i < NCF; ++i) cm[i] = 0.0;
    cm[0] = dd[NCF - 1];
    int deg = 0;
    for (int k = NCF - 2; k >= 0; --k) {
        for (int d = deg + 1; d >= 0; --d) {
            double hi = (d >= 1) ? cm[d - 1] : 0.0;
            double lo = (d <= deg) ? cm[d] : 0.0;
            cm[d] = hi - vn[k] * lo;
        }
        cm[0] += dd[k];
        ++deg;
    }
    Coeffs cf;
    for (int d = 0; d < NCF; ++d) cf.c[d] = (float)cm[d];

    dim3 grid(BATCH / TI, OUT / TB, MB);      // (8, 16, 8) = 1024 CTAs
    dnm_main_kernel<<<grid, 256>>>(x, w, cf);
    dnm_norm_kernel<<<BATCH, OUT>>>(z);
}

// round 13
// speedup vs baseline: 1.1023x; 1.1023x over previous
#include <cuda_runtime.h>
#include <cuda_fp16.h>
#include <math.h>

#define BATCH 128
#define OUT   256
#define MB    8      // M branches
#define INS   512    // inner size
#define TI    16     // batch tile
#define TB    16     // out tile
#define KC    256    // k chunk (f16 smem) -> 16.9KB -> 8 CTAs/SM -> single wave
#define KP    (KC + 8)

// scratch: S[i][b][j] - 256 stored as f16 (|S-256| <~ 40, ulp error ~6e-5 rel)
__device__ __half g_Sh[BATCH * OUT * MB];

__device__ __forceinline__ __half2 tanh_h2(__half2 v) {
    unsigned r, a = *(unsigned*)&v;
    asm("tanh.approx.f16x2 %0, %1;" : "=r"(r) : "r"(a));
    return *(__half2*)&r;
}

// One CTA = (16 i x 16 b) tile of ONE branch j, k chunked at 256.
// sigmoid(u) = 0.5 + 0.5*tanh(u/2); x prescaled by 0.5 at f16-convert time.
// __launch_bounds__(256, 8): 32 regs -> 8 CTAs/SM -> all 1024 CTAs in 1 wave.
__global__ __launch_bounds__(256, 8) void dnm_main_kernel(
    const float* __restrict__ x,
    const float* __restrict__ w)
{
    __shared__ __half xs[TI][KP];
    __shared__ __half ws[TB][KP];

    const int tid = threadIdx.x;
    const int tx  = tid & 15;
    const int ty  = tid >> 4;
    const int i0  = blockIdx.x * TI;
    const int b0  = blockIdx.y * TB;
    const int j   = blockIdx.z;        // 1024 CTAs total

    float acc0 = 0.0f, acc1 = 0.0f;

    #pragma unroll 1
    for (int kc = 0; kc < INS; kc += KC) {
        // ---- cooperative load + f32->f16 convert (x scaled by 0.5) ----
        #pragma unroll
        for (int it = 0; it < (TI * KC) / (4 * 256); ++it) {   // 4 iters
            int idx = it * 256 + tid;
            int r = idx >> 6, c = (idx & 63) << 2;             // 64 float4/row
            float4 v = *(const float4*)&x[((size_t)(i0 + r) * MB + j) * INS + kc + c];
            *(__half2*)&xs[r][c]     = __floats2half2_rn(0.5f * v.x, 0.5f * v.y);
            *(__half2*)&xs[r][c + 2] = __floats2half2_rn(0.5f * v.z, 0.5f * v.w);
        }
        #pragma unroll
        for (int it = 0; it < (TB * KC) / (4 * 256); ++it) {
            int idx = it * 256 + tid;
            int r = idx >> 6, c = (idx & 63) << 2;
            float4 v = *(const float4*)&w[((size_t)(b0 + r) * MB + j) * INS + kc + c];
            *(__half2*)&ws[r][c]     = __floats2half2_rn(v.x, v.y);
            *(__half2*)&ws[r][c + 2] = __floats2half2_rn(v.z, v.w);
        }
        __syncthreads();

        // ---- main loop: 4 elements / lane / iter (r4 proven body) ----
        const __half* xr = &xs[tx][0];
        const __half* wr = &ws[ty][0];
        #pragma unroll 16
        for (int k = 0; k < KC; k += 4) {
            uint2 xv = *(const uint2*)&xr[k];
            uint2 wv = *(const uint2*)&wr[k];
            __half2 t01 = __hmul2(*(__half2*)&xv.x, *(__half2*)&wv.x);
            __half2 t23 = __hmul2(*(__half2*)&xv.y, *(__half2*)&wv.y);
            __half2 h01 = tanh_h2(t01);
            __half2 h23 = tanh_h2(t23);
            __half2 s   = __hadd2(h01, h23);
            acc0 += __low2float(s);
            acc1 += __high2float(s);
        }
        __syncthreads();
    }

    // S - 256 = 0.5 * sum_k tanh  (stored as f16)
    float Sm = 0.5f * (acc0 + acc1);
    g_Sh[((size_t)(i0 + tx) * OUT + (b0 + ty)) * MB + j] = __float2half_rn(Sm);
}

// Per-row normalize with fused product-of-branches; reads f16 (S-256).
// zn = v/total has mean exactly 1/256; ddof=1 var = (sum zn^2 - 1/256)/255.
__global__ __launch_bounds__(OUT) void dnm_norm_kernel(float* __restrict__ out)
{
    const int i = blockIdx.x;
    const int b = threadIdx.x;

    const __half2* sp = (const __half2*)&g_Sh[((size_t)i * OUT + b) * MB];
    uint4 raw = __ldcg((const uint4*)sp);
    const __half2* h = (const __half2*)&raw;
    float v = 1.0f;
    #pragma unroll
    for (int q = 0; q < 4; ++q) {
        float2 f = __half22float2(h[q]);
        v *= (256.0f + f.x) * (256.0f + f.y);
    }

    // v ~ 256^8 = 2^64 -> scale before squaring (stats are scale-invariant)
    float vs = v * 0x1p-64f;

    float s1 = vs, s2 = vs * vs;
    #pragma unroll
    for (int off = 16; off > 0; off >>= 1) {
        s1 += __shfl_xor_sync(0xffffffffu, s1, off);
        s2 += __shfl_xor_sync(0xffffffffu, s2, off);
    }
    __shared__ float r1[8], r2[8];
    if ((b & 31) == 0) { r1[b >> 5] = s1; r2[b >> 5] = s2; }
    __syncthreads();

    float total = 0.0f, sq = 0.0f;
    #pragma unroll
    for (int q = 0; q < 8; ++q) { total += r1[q]; sq += r2[q]; }

    float inv = 1.0f / total;
    float zn  = vs * inv;
    float var = (sq * inv * inv - 1.0f / 256.0f) * (1.0f / 255.0f);
    out[(size_t)i * OUT + b] = (zn - 1.0f / 256.0f) * rsqrtf(var);
}

extern "C" void kernel_launch(void* const* d_in, const int* in_sizes, int n_in,
                              void* d_out, int out_size)
{
    const float* x = (const float*)d_in[0];   // (128, 8, 512)
    const float* w = (const float*)d_in[1];   // (256, 8, 512)
    float* z = (float*)d_out;                 // (128, 256)

    dim3 grid(BATCH / TI, OUT / TB, MB);      // (8, 16, 8) = 1024 CTAs
    dnm_main_kernel<<<grid, 256>>>(x, w);
    dnm_norm_kernel<<<BATCH, OUT>>>(z);
}

// round 14
// speedup vs baseline: 1.1113x; 1.0081x over previous
#include <cuda_runtime.h>
#include <cuda_fp16.h>
#include <math.h>

#define BATCH 128
#define OUT   256
#define MB    8      // M branches
#define INS   512    // inner size
#define TI    16     // batch tile
#define TB    16     // out tile
#define KC    256    // k chunk (f16 smem) -> 16.9KB/CTA
#define KP    (KC + 8)

// scratch: S[i][b][j] = sum_k sigmoid(x[i,j,k]*W[b,j,k])
__device__ float g_S[BATCH * OUT * MB];

__device__ __forceinline__ __half2 tanh_h2(__half2 v) {
    unsigned r, a = *(unsigned*)&v;
    asm("tanh.approx.f16x2 %0, %1;" : "=r"(r) : "r"(a));
    return *(__half2*)&r;
}

// One CTA = (16 i x 16 b) tile of ONE branch j, k chunked at 256.
// sigmoid(u) = 0.5 + 0.5*tanh(u/2); x prescaled by 0.5 at f16-convert time.
// __launch_bounds__(256, 7): 36 regs -> 7 CTAs/SM -> 1036 slots >= 1024 CTAs
// -> single wave, without the spills the 32-reg cap caused (r10/r13).
__global__ __launch_bounds__(256, 7) void dnm_main_kernel(
    const float* __restrict__ x,
    const float* __restrict__ w)
{
    __shared__ __half xs[TI][KP];
    __shared__ __half ws[TB][KP];

    const int tid = threadIdx.x;
    const int tx  = tid & 15;
    const int ty  = tid >> 4;
    const int i0  = blockIdx.x * TI;
    const int b0  = blockIdx.y * TB;
    const int j   = blockIdx.z;        // 1024 CTAs total

    float acc0 = 0.0f, acc1 = 0.0f;

    #pragma unroll 1
    for (int kc = 0; kc < INS; kc += KC) {
        // ---- cooperative load + f32->f16 convert (x scaled by 0.5) ----
        #pragma unroll
        for (int it = 0; it < (TI * KC) / (4 * 256); ++it) {   // 4 iters
            int idx = it * 256 + tid;
            int r = idx >> 6, c = (idx & 63) << 2;             // 64 float4/row
            float4 v = *(const float4*)&x[((size_t)(i0 + r) * MB + j) * INS + kc + c];
            *(__half2*)&xs[r][c]     = __floats2half2_rn(0.5f * v.x, 0.5f * v.y);
            *(__half2*)&xs[r][c + 2] = __floats2half2_rn(0.5f * v.z, 0.5f * v.w);
        }
        #pragma unroll
        for (int it = 0; it < (TB * KC) / (4 * 256); ++it) {
            int idx = it * 256 + tid;
            int r = idx >> 6, c = (idx & 63) << 2;
            float4 v = *(const float4*)&w[((size_t)(b0 + r) * MB + j) * INS + kc + c];
            *(__half2*)&ws[r][c]     = __floats2half2_rn(v.x, v.y);
            *(__half2*)&ws[r][c + 2] = __floats2half2_rn(v.z, v.w);
        }
        __syncthreads();

        // ---- main loop: 4 elements / lane / iter (r4 proven body) ----
        const __half* xr = &xs[tx][0];
        const __half* wr = &ws[ty][0];
        #pragma unroll 16
        for (int k = 0; k < KC; k += 4) {
            uint2 xv = *(const uint2*)&xr[k];
            uint2 wv = *(const uint2*)&wr[k];
            __half2 t01 = __hmul2(*(__half2*)&xv.x, *(__half2*)&wv.x);
            __half2 t23 = __hmul2(*(__half2*)&xv.y, *(__half2*)&wv.y);
            __half2 h01 = tanh_h2(t01);
            __half2 h23 = tanh_h2(t23);
            __half2 s   = __hadd2(h01, h23);
            acc0 += __low2float(s);
            acc1 += __high2float(s);
        }
        __syncthreads();
    }

    // sum_k sigmoid = 0.5 * sum_k tanh + 256
    float S = fmaf(0.5f, acc0 + acc1, 0.5f * (float)INS);
    g_S[((size_t)(i0 + tx) * OUT + (b0 + ty)) * MB + j] = S;

    // PDL: let the dependent (norm) kernel begin its launch/prologue ramp.
    asm volatile("griddepcontrol.launch_dependents;");
}

// Per-row normalize with fused product-of-branches (r4 proven version).
// Launched with ProgrammaticStreamSerialization: prologue overlaps main's
// tail; griddepcontrol.wait blocks until main's writes are visible.
__global__ __launch_bounds__(OUT) void dnm_norm_kernel(float* __restrict__ out)
{
    asm volatile("griddepcontrol.wait;");

    const int i = blockIdx.x;
    const int b = threadIdx.x;

    const float* sp = &g_S[((size_t)i * OUT + b) * MB];
    float4 a = *(const float4*)sp;
    float4 c = *(const float4*)(sp + 4);
    float v = ((a.x * a.y) * (a.z * a.w)) * ((c.x * c.y) * (c.z * c.w));

    // v ~ 256^8 = 2^64 -> scale before squaring (stats are scale-invariant)
    float vs = v * 0x1p-64f;

    float s1 = vs, s2 = vs * vs;
    #pragma unroll
    for (int off = 16; off > 0; off >>= 1) {
        s1 += __shfl_xor_sync(0xffffffffu, s1, off);
        s2 += __shfl_xor_sync(0xffffffffu, s2, off);
    }
    __shared__ float r1[8], r2[8];
    if ((b & 31) == 0) { r1[b >> 5] = s1; r2[b >> 5] = s2; }
    __syncthreads();

    float total = 0.0f, sq = 0.0f;
    #pragma unroll
    for (int q = 0; q < 8; ++q) { total += r1[q]; sq += r2[q]; }

    float inv = 1.0f / total;
    float zn  = vs * inv;
    float var = (sq * inv * inv - 1.0f / 256.0f) * (1.0f / 255.0f);
    out[(size_t)i * OUT + b] = (zn - 1.0f / 256.0f) * rsqrtf(var);
}

extern "C" void kernel_launch(void* const* d_in, const int* in_sizes, int n_in,
                              void* d_out, int out_size)
{
    const float* x = (const float*)d_in[0];   // (128, 8, 512)
    const float* w = (const float*)d_in[1];   // (256, 8, 512)
    float* z = (float*)d_out;                 // (128, 256)

    dim3 grid(BATCH / TI, OUT / TB, MB);      // (8, 16, 8) = 1024 CTAs
    dnm_main_kernel<<<grid, 256>>>(x, w);

    // norm with Programmatic Dependent Launch (overlap launch ramp with tail)
    cudaLaunchConfig_t cfg = {};
    cfg.gridDim  = dim3(BATCH, 1, 1);
    cfg.blockDim = dim3(OUT, 1, 1);
    cudaLaunchAttribute attr[1];
    attr[0].id = cudaLaunchAttributeProgrammaticStreamSerialization;
    attr[0].val.programmaticStreamSerializationAllowed = 1;
    cfg.attrs = attr;
    cfg.numAttrs = 1;
    cudaLaunchKernelEx(&cfg, dnm_norm_kernel, z);
}

// round 15
// speedup vs baseline: 1.1633x; 1.0468x over previous
#include <cuda_runtime.h>
#include <cuda_fp16.h>
#include <math.h>

#define BATCH 128
#define OUT   256
#define MB    8      // M branches
#define INS   512    // inner size (full K in smem, f16)
#define TI    16     // batch tile
#define TB    16     // out tile
#define KP    (INS + 8)

// scratch: S[i][b][j] = sum_k sigmoid(x[i,j,k]*W[b,j,k])
__device__ float g_S[BATCH * OUT * MB];

__device__ __forceinline__ __half2 tanh_h2(__half2 v) {
    unsigned r, a = *(unsigned*)&v;
    asm("tanh.approx.f16x2 %0, %1;" : "=r"(r) : "r"(a));
    return *(__half2*)&r;
}

// r4 main kernel, byte-for-byte (fastest measured: ~32.9us), plus one
// trailing PDL signal. No launch_bounds cap (caps spill: r10/r13/r14),
// no K chunking (chunking costs more than the wave tail: r9/r13/r14).
__global__ __launch_bounds__(256) void dnm_main_kernel(
    const float* __restrict__ x,
    const float* __restrict__ w)
{
    __shared__ __half xs[TI][KP];
    __shared__ __half ws[TB][KP];

    const int tid = threadIdx.x;
    const int tx  = tid & 15;
    const int ty  = tid >> 4;
    const int i0  = blockIdx.x * TI;
    const int b0  = blockIdx.y * TB;
    const int j   = blockIdx.z;        // 1024 CTAs total

    // ---- cooperative load + f32->f16 convert (x scaled by 0.5) ----
    #pragma unroll
    for (int it = 0; it < (TI * INS) / (4 * 256); ++it) {
        int idx = it * 256 + tid;
        int r = idx >> 7, c = (idx & 127) << 2;   // 128 float4 per row
        float4 v = *(const float4*)&x[((size_t)(i0 + r) * MB + j) * INS + c];
        *(__half2*)&xs[r][c]     = __floats2half2_rn(0.5f * v.x, 0.5f * v.y);
        *(__half2*)&xs[r][c + 2] = __floats2half2_rn(0.5f * v.z, 0.5f * v.w);
    }
    #pragma unroll
    for (int it = 0; it < (TB * INS) / (4 * 256); ++it) {
        int idx = it * 256 + tid;
        int r = idx >> 7, c = (idx & 127) << 2;
        float4 v = *(const float4*)&w[((size_t)(b0 + r) * MB + j) * INS + c];
        *(__half2*)&ws[r][c]     = __floats2half2_rn(v.x, v.y);
        *(__half2*)&ws[r][c + 2] = __floats2half2_rn(v.z, v.w);
    }
    __syncthreads();

    // ---- main loop: 4 elements / lane / iter ----
    float acc0 = 0.0f, acc1 = 0.0f;
    const __half* xr = &xs[tx][0];
    const __half* wr = &ws[ty][0];

    #pragma unroll 16
    for (int k = 0; k < INS; k += 4) {
        uint2 xv = *(const uint2*)&xr[k];
        uint2 wv = *(const uint2*)&wr[k];
        __half2 t01 = __hmul2(*(__half2*)&xv.x, *(__half2*)&wv.x);
        __half2 t23 = __hmul2(*(__half2*)&xv.y, *(__half2*)&wv.y);
        __half2 h01 = tanh_h2(t01);
        __half2 h23 = tanh_h2(t23);
        __half2 s   = __hadd2(h01, h23);
        acc0 += __low2float(s);
        acc1 += __high2float(s);
    }

    // sum_k sigmoid = 0.5 * sum_k tanh + 256
    float S = fmaf(0.5f, acc0 + acc1, 0.5f * (float)INS);
    g_S[((size_t)(i0 + tx) * OUT + (b0 + ty)) * MB + j] = S;

    // PDL: allow the dependent (norm) kernel's launch ramp to overlap our tail.
    asm volatile("griddepcontrol.launch_dependents;");
}

// Per-row normalize with fused product-of-branches (r4 proven version),
// gated by griddepcontrol.wait (PDL).
__global__ __launch_bounds__(OUT) void dnm_norm_kernel(float* __restrict__ out)
{
    asm volatile("griddepcontrol.wait;");

    const int i = blockIdx.x;
    const int b = threadIdx.x;

    const float* sp = &g_S[((size_t)i * OUT + b) * MB];
    float4 a = *(const float4*)sp;
    float4 c = *(const float4*)(sp + 4);
    float v = ((a.x * a.y) * (a.z * a.w)) * ((c.x * c.y) * (c.z * c.w));

    // v ~ 256^8 = 2^64 -> scale before squaring (stats are scale-invariant)
    float vs = v * 0x1p-64f;

    float s1 = vs, s2 = vs * vs;
    #pragma unroll
    for (int off = 16; off > 0; off >>= 1) {
        s1 += __shfl_xor_sync(0xffffffffu, s1, off);
        s2 += __shfl_xor_sync(0xffffffffu, s2, off);
    }
    __shared__ float r1[8], r2[8];
    if ((b & 31) == 0) { r1[b >> 5] = s1; r2[b >> 5] = s2; }
    __syncthreads();

    float total = 0.0f, sq = 0.0f;
    #pragma unroll
    for (int q = 0; q < 8; ++q) { total += r1[q]; sq += r2[q]; }

    float inv = 1.0f / total;
    float zn  = vs * inv;
    float var = (sq * inv * inv - 1.0f / 256.0f) * (1.0f / 255.0f);
    out[(size_t)i * OUT + b] = (zn - 1.0f / 256.0f) * rsqrtf(var);
}

extern "C" void kernel_launch(void* const* d_in, const int* in_sizes, int n_in,
                              void* d_out, int out_size)
{
    const float* x = (const float*)d_in[0];   // (128, 8, 512)
    const float* w = (const float*)d_in[1];   // (256, 8, 512)
    float* z = (float*)d_out;                 // (128, 256)

    dim3 grid(BATCH / TI, OUT / TB, MB);      // (8, 16, 8) = 1024 CTAs
    dnm_main_kernel<<<grid, 256>>>(x, w);

    // norm with Programmatic Dependent Launch (overlap launch ramp with tail)
    cudaLaunchConfig_t cfg = {};
    cfg.gridDim  = dim3(BATCH, 1, 1);
    cfg.blockDim = dim3(OUT, 1, 1);
    cudaLaunchAttribute attr[1];
    attr[0].id = cudaLaunchAttributeProgrammaticStreamSerialization;
    attr[0].val.programmaticStreamSerializationAllowed = 1;
    cfg.attrs = attr;
    cfg.numAttrs = 1;
    cudaLaunchKernelEx(&cfg, dnm_norm_kernel, z);
}